// round 1
// baseline (speedup 1.0000x reference)
#include <cuda_runtime.h>
#include <math.h>

#define Bdim 32
#define Pdim 1024
#define Ndim 1024
#define Edim 128
#define HQdim 128
#define SQRT_E_F 11.313708498984761f
#define CLIP_F 10.0f

// ---------------- scratch (device globals; no allocations allowed) ----------
__device__ float g_ek  [Bdim * (size_t)Ndim * HQdim];   // exp(k)
__device__ float g_ekv [Bdim * (size_t)Ndim * HQdim];   // exp(k)*v
__device__ float g_sigq[Bdim * (size_t)Pdim * HQdim];   // sigmoid(q)
__device__ float g_num [Bdim * (size_t)Pdim * HQdim];
__device__ float g_den [Bdim * (size_t)Pdim * HQdim];
__device__ float g_aft [Bdim * (size_t)Pdim * HQdim];   // AFT_out
__device__ float g_rowsum[Bdim * Pdim];

__device__ __forceinline__ float nan2num(float x) {
    if (isnan(x)) return 0.0f;
    if (isinf(x)) return x > 0.0f ? 3.402823466e38f : -3.402823466e38f;
    return x;
}

// ============================================================================
// K1: k = enc @ Wk ; v = enc @ Wv ; ek = exp(k) ; ekv = ek*v
// block: (b, n-tile of 64). 256 threads, thread tile 4x8, dual accumulators.
// ============================================================================
__global__ __launch_bounds__(256) void k_proj_kv(
    const float* __restrict__ enc,
    const float* __restrict__ Wk,
    const float* __restrict__ Wv)
{
    const int b  = blockIdx.x;
    const int n0 = blockIdx.y * 64;
    const int tid = threadIdx.x;
    const int tc = tid & 15;   // 16 col groups of 8
    const int tr = tid >> 4;   // 16 row groups of 4

    __shared__ float As[16][65];     // [k][m] transposed
    __shared__ float WkS[16][128];
    __shared__ float WvS[16][128];

    float accK[4][8], accV[4][8];
#pragma unroll
    for (int i = 0; i < 4; i++)
#pragma unroll
        for (int j = 0; j < 8; j++) { accK[i][j] = 0.f; accV[i][j] = 0.f; }

    const float* Abase = enc + ((size_t)b * Ndim + n0) * Edim;

    for (int k0 = 0; k0 < Edim; k0 += 16) {
        // load A tile 64x16 -> transposed
        {
            int row = tid >> 2, seg = tid & 3;
            float4 v = *reinterpret_cast<const float4*>(Abase + (size_t)row * Edim + k0 + seg * 4);
            As[seg * 4 + 0][row] = v.x;
            As[seg * 4 + 1][row] = v.y;
            As[seg * 4 + 2][row] = v.z;
            As[seg * 4 + 3][row] = v.w;
        }
        // load W tiles 16x128 (each 512 float4, 2 per thread)
#pragma unroll
        for (int i = 0; i < 2; i++) {
            int f = tid + i * 256;
            int e = f >> 5, c4 = f & 31;
            *reinterpret_cast<float4*>(&WkS[e][c4 * 4]) =
                *reinterpret_cast<const float4*>(Wk + (size_t)(k0 + e) * HQdim + c4 * 4);
            *reinterpret_cast<float4*>(&WvS[e][c4 * 4]) =
                *reinterpret_cast<const float4*>(Wv + (size_t)(k0 + e) * HQdim + c4 * 4);
        }
        __syncthreads();
#pragma unroll
        for (int k = 0; k < 16; k++) {
            float a[4];
#pragma unroll
            for (int i = 0; i < 4; i++) a[i] = As[k][tr * 4 + i];
            float4 wk0 = *reinterpret_cast<const float4*>(&WkS[k][tc * 8]);
            float4 wk1 = *reinterpret_cast<const float4*>(&WkS[k][tc * 8 + 4]);
            float4 wv0 = *reinterpret_cast<const float4*>(&WvS[k][tc * 8]);
            float4 wv1 = *reinterpret_cast<const float4*>(&WvS[k][tc * 8 + 4]);
            float wk[8] = {wk0.x, wk0.y, wk0.z, wk0.w, wk1.x, wk1.y, wk1.z, wk1.w};
            float wv[8] = {wv0.x, wv0.y, wv0.z, wv0.w, wv1.x, wv1.y, wv1.z, wv1.w};
#pragma unroll
            for (int i = 0; i < 4; i++)
#pragma unroll
                for (int j = 0; j < 8; j++) {
                    accK[i][j] += a[i] * wk[j];
                    accV[i][j] += a[i] * wv[j];
                }
        }
        __syncthreads();
    }
    // epilogue
#pragma unroll
    for (int i = 0; i < 4; i++) {
        int n = n0 + tr * 4 + i;
        size_t base = ((size_t)b * Ndim + n) * HQdim + tc * 8;
        float e[8];
#pragma unroll
        for (int j = 0; j < 8; j++) e[j] = expf(accK[i][j]);
        float4 e0 = {e[0], e[1], e[2], e[3]};
        float4 e1 = {e[4], e[5], e[6], e[7]};
        float4 v0 = {e[0] * accV[i][0], e[1] * accV[i][1], e[2] * accV[i][2], e[3] * accV[i][3]};
        float4 v1 = {e[4] * accV[i][4], e[5] * accV[i][5], e[6] * accV[i][6], e[7] * accV[i][7]};
        *reinterpret_cast<float4*>(&g_ek[base])      = e0;
        *reinterpret_cast<float4*>(&g_ek[base + 4])  = e1;
        *reinterpret_cast<float4*>(&g_ekv[base])     = v0;
        *reinterpret_cast<float4*>(&g_ekv[base + 4]) = v1;
    }
}

// ============================================================================
// K2: q = q1@Wq1 + q2@Wq2 + last@Wql[:128] + load*Wql[128] + left*Wql[129]
//     sigq = sigmoid(q)
// ============================================================================
__global__ __launch_bounds__(256) void k_proj_q(
    const float* __restrict__ eq1,
    const float* __restrict__ eq2,
    const float* __restrict__ elast,
    const float* __restrict__ Wq1,
    const float* __restrict__ Wq2,
    const float* __restrict__ Wql,
    const float* __restrict__ load_,
    const float* __restrict__ left_)
{
    const int b  = blockIdx.x;
    const int p0 = blockIdx.y * 64;
    const int tid = threadIdx.x;
    const int tc = tid & 15;
    const int tr = tid >> 4;

    __shared__ float As[16][65];
    __shared__ float Ws[16][128];

    float acc[4][8];
#pragma unroll
    for (int i = 0; i < 4; i++)
#pragma unroll
        for (int j = 0; j < 8; j++) acc[i][j] = 0.f;

    const float* Aptr[3] = {eq1, eq2, elast};
    const float* Wptr[3] = {Wq1, Wq2, Wql};

    for (int m = 0; m < 3; m++) {
        const float* Ab = Aptr[m] + ((size_t)b * Pdim + p0) * Edim;
        const float* Wb = Wptr[m];
        for (int k0 = 0; k0 < Edim; k0 += 16) {
            {
                int row = tid >> 2, seg = tid & 3;
                float4 v = *reinterpret_cast<const float4*>(Ab + (size_t)row * Edim + k0 + seg * 4);
                As[seg * 4 + 0][row] = v.x;
                As[seg * 4 + 1][row] = v.y;
                As[seg * 4 + 2][row] = v.z;
                As[seg * 4 + 3][row] = v.w;
            }
#pragma unroll
            for (int i = 0; i < 2; i++) {
                int f = tid + i * 256;
                int e = f >> 5, c4 = f & 31;
                *reinterpret_cast<float4*>(&Ws[e][c4 * 4]) =
                    *reinterpret_cast<const float4*>(Wb + (size_t)(k0 + e) * HQdim + c4 * 4);
            }
            __syncthreads();
#pragma unroll
            for (int k = 0; k < 16; k++) {
                float a[4];
#pragma unroll
                for (int i = 0; i < 4; i++) a[i] = As[k][tr * 4 + i];
                float4 w0 = *reinterpret_cast<const float4*>(&Ws[k][tc * 8]);
                float4 w1 = *reinterpret_cast<const float4*>(&Ws[k][tc * 8 + 4]);
                float w[8] = {w0.x, w0.y, w0.z, w0.w, w1.x, w1.y, w1.z, w1.w};
#pragma unroll
                for (int i = 0; i < 4; i++)
#pragma unroll
                    for (int j = 0; j < 8; j++) acc[i][j] += a[i] * w[j];
            }
            __syncthreads();
        }
    }
    // epilogue: + load*Wql[128] + left*Wql[129], sigmoid
    int d0 = tc * 8;
    float wl[8], wr[8];
#pragma unroll
    for (int j = 0; j < 8; j++) {
        wl[j] = Wql[(size_t)128 * HQdim + d0 + j];
        wr[j] = Wql[(size_t)129 * HQdim + d0 + j];
    }
#pragma unroll
    for (int i = 0; i < 4; i++) {
        int p = p0 + tr * 4 + i;
        float lo = load_[(size_t)b * Pdim + p];
        float le = left_[(size_t)b * Pdim + p];
        float s[8];
#pragma unroll
        for (int j = 0; j < 8; j++) {
            float q = acc[i][j] + lo * wl[j] + le * wr[j];
            s[j] = 1.0f / (1.0f + expf(-q));
        }
        size_t base = ((size_t)b * Pdim + p) * HQdim + d0;
        float4 s0 = {s[0], s[1], s[2], s[3]};
        float4 s1 = {s[4], s[5], s[6], s[7]};
        *reinterpret_cast<float4*>(&g_sigq[base])     = s0;
        *reinterpret_cast<float4*>(&g_sigq[base + 4]) = s1;
    }
}

// ============================================================================
// K3: e_bias = exp(ls*alpha*(-cur_dist) + ninf)  (computed on the fly)
//     num = e_bias @ ekv ; den = e_bias @ ek     (fused: BN = 256)
// block: (b, p-tile of 64). 256 threads, thread tile 8x8.
// ============================================================================
__global__ __launch_bounds__(256) void k_aft(
    const float* __restrict__ cur_dist,
    const float* __restrict__ ninf,
    const float* __restrict__ ls,
    const float* __restrict__ aalpha)
{
    const int b  = blockIdx.x;
    const int p0 = blockIdx.y * 64;
    const int tid = threadIdx.x;
    const int tc = tid & 31;   // 32 col groups of 8  (0..15 -> num, 16..31 -> den)
    const int tr = tid >> 5;   // 8 row groups of 8

    __shared__ float As[16][65];
    __shared__ float Bs[16][256];

    const float c2 = ls[0] * aalpha[0];

    float acc[8][8];
#pragma unroll
    for (int i = 0; i < 8; i++)
#pragma unroll
        for (int j = 0; j < 8; j++) acc[i][j] = 0.f;

    const float* cdb = cur_dist + ((size_t)b * Pdim + p0) * Ndim;
    const float* nmb = ninf     + ((size_t)b * Pdim + p0) * Ndim;

    for (int k0 = 0; k0 < Ndim; k0 += 16) {
        // A tile: exp(-c2*cd + nm), transposed
        {
            int row = tid >> 2, seg = tid & 3;
            float4 cd = *reinterpret_cast<const float4*>(cdb + (size_t)row * Ndim + k0 + seg * 4);
            float4 nm = *reinterpret_cast<const float4*>(nmb + (size_t)row * Ndim + k0 + seg * 4);
            As[seg * 4 + 0][row] = expf(nm.x - c2 * cd.x);
            As[seg * 4 + 1][row] = expf(nm.y - c2 * cd.y);
            As[seg * 4 + 2][row] = expf(nm.z - c2 * cd.z);
            As[seg * 4 + 3][row] = expf(nm.w - c2 * cd.w);
        }
        // B tile 16x256 : cols 0..127 <- ekv, 128..255 <- ek  (4 float4/thread)
#pragma unroll
        for (int i = 0; i < 4; i++) {
            int f = tid + i * 256;
            int nr = f >> 6, c4 = f & 63;
            int d4 = c4 * 4;
            const float* src = (d4 < 128)
                ? (g_ekv + ((size_t)b * Ndim + k0 + nr) * HQdim + d4)
                : (g_ek  + ((size_t)b * Ndim + k0 + nr) * HQdim + (d4 - 128));
            *reinterpret_cast<float4*>(&Bs[nr][d4]) = *reinterpret_cast<const float4*>(src);
        }
        __syncthreads();
#pragma unroll
        for (int k = 0; k < 16; k++) {
            float a[8];
#pragma unroll
            for (int i = 0; i < 8; i++) a[i] = As[k][tr * 8 + i];
            float4 b0 = *reinterpret_cast<const float4*>(&Bs[k][tc * 8]);
            float4 b1 = *reinterpret_cast<const float4*>(&Bs[k][tc * 8 + 4]);
            float bb[8] = {b0.x, b0.y, b0.z, b0.w, b1.x, b1.y, b1.z, b1.w};
#pragma unroll
            for (int i = 0; i < 8; i++)
#pragma unroll
                for (int j = 0; j < 8; j++) acc[i][j] += a[i] * bb[j];
        }
        __syncthreads();
    }
    // epilogue
    int col0 = tc * 8;
#pragma unroll
    for (int i = 0; i < 8; i++) {
        int p = p0 + tr * 8 + i;
        size_t base = ((size_t)b * Pdim + p) * HQdim;
        float* dst = (col0 < 128) ? (g_num + base + col0) : (g_den + base + col0 - 128);
        float4 c0 = {acc[i][0], acc[i][1], acc[i][2], acc[i][3]};
        float4 c1 = {acc[i][4], acc[i][5], acc[i][6], acc[i][7]};
        *reinterpret_cast<float4*>(dst)     = c0;
        *reinterpret_cast<float4*>(dst + 4) = c1;
    }
}

// ============================================================================
// K3b: AFT_out = sigq * nan_to_num(num) / (nan_to_num(den) + 1e-20)
// ============================================================================
__global__ void k_combine()
{
    const size_t total4 = (size_t)Bdim * Pdim * HQdim / 4;
    for (size_t i = (size_t)blockIdx.x * blockDim.x + threadIdx.x; i < total4;
         i += (size_t)gridDim.x * blockDim.x) {
        float4 nu = *reinterpret_cast<const float4*>(g_num  + i * 4);
        float4 de = *reinterpret_cast<const float4*>(g_den  + i * 4);
        float4 sg = *reinterpret_cast<const float4*>(g_sigq + i * 4);
        float4 o;
        o.x = sg.x * nan2num(nu.x) / (nan2num(de.x) + 1e-20f);
        o.y = sg.y * nan2num(nu.y) / (nan2num(de.y) + 1e-20f);
        o.z = sg.z * nan2num(nu.z) / (nan2num(de.z) + 1e-20f);
        o.w = sg.w * nan2num(nu.w) / (nan2num(de.w) + 1e-20f);
        *reinterpret_cast<float4*>(g_aft + i * 4) = o;
    }
}

// ============================================================================
// K4: score = AFT_out @ enc_nodes^T ; fused scale, dist bias, tanh clip, exp.
// Writes unnormalized exp(logits) to out and per-row sums to g_rowsum.
// (Logits clipped to [-10,10] -> exp is fp32-safe without max subtraction.)
// block: (b, p-tile of 64). 128 threads, thread tile 8x8, loop over 8 n-tiles.
// ============================================================================
__global__ __launch_bounds__(128) void k_score(
    const float* __restrict__ enc,
    const float* __restrict__ cur_dist,
    const float* __restrict__ ninf,
    const float* __restrict__ ls,
    const float* __restrict__ palpha,
    float* __restrict__ out)
{
    const int b  = blockIdx.x;
    const int p0 = blockIdx.y * 64;
    const int tid = threadIdx.x;
    const int tc = tid & 15;   // 16 col groups of 8
    const int tr = tid >> 4;   // 8 row groups of 8

    __shared__ float As[128][65];   // AFT_out transposed: [e][m]
    __shared__ float Bs[16][132];   // enc transposed chunk: [e][n]
    __shared__ float Red[64][17];

    const float cp = ls[0] * palpha[0];

    // load full A tile (64 rows x 128) transposed: 16 float4 per thread
    {
        const float* Ab = g_aft + ((size_t)b * Pdim + p0) * HQdim;
#pragma unroll
        for (int i = 0; i < 16; i++) {
            int f = tid + i * 128;
            int row = f >> 5, c4 = f & 31;
            float4 v = *reinterpret_cast<const float4*>(Ab + (size_t)row * HQdim + c4 * 4);
            As[c4 * 4 + 0][row] = v.x;
            As[c4 * 4 + 1][row] = v.y;
            As[c4 * 4 + 2][row] = v.z;
            As[c4 * 4 + 3][row] = v.w;
        }
    }

    float rsum[8];
#pragma unroll
    for (int i = 0; i < 8; i++) rsum[i] = 0.f;

    for (int nt = 0; nt < Ndim / 128; nt++) {
        float acc[8][8];
#pragma unroll
        for (int i = 0; i < 8; i++)
#pragma unroll
            for (int j = 0; j < 8; j++) acc[i][j] = 0.f;

        for (int k0 = 0; k0 < Edim; k0 += 16) {
            __syncthreads();
            // load B chunk: 128 n-rows x 16 e, transposed (4 float4/thread)
#pragma unroll
            for (int i = 0; i < 4; i++) {
                int f = tid + i * 128;
                int nrow = f >> 2, seg = f & 3;
                float4 v = *reinterpret_cast<const float4*>(
                    enc + ((size_t)b * Ndim + nt * 128 + nrow) * Edim + k0 + seg * 4);
                Bs[seg * 4 + 0][nrow] = v.x;
                Bs[seg * 4 + 1][nrow] = v.y;
                Bs[seg * 4 + 2][nrow] = v.z;
                Bs[seg * 4 + 3][nrow] = v.w;
            }
            __syncthreads();
#pragma unroll
            for (int k = 0; k < 16; k++) {
                int ke = k0 + k;
                float a[8];
#pragma unroll
                for (int i = 0; i < 8; i++) a[i] = As[ke][tr * 8 + i];
                float4 b0 = *reinterpret_cast<const float4*>(&Bs[k][tc * 8]);
                float4 b1 = *reinterpret_cast<const float4*>(&Bs[k][tc * 8 + 4]);
                float bb[8] = {b0.x, b0.y, b0.z, b0.w, b1.x, b1.y, b1.z, b1.w};
#pragma unroll
                for (int i = 0; i < 8; i++)
#pragma unroll
                    for (int j = 0; j < 8; j++) acc[i][j] += a[i] * bb[j];
            }
        }
        // epilogue for this n-tile
#pragma unroll
        for (int i = 0; i < 8; i++) {
            int p = p0 + tr * 8 + i;
            size_t rb = ((size_t)b * Pdim + p) * Ndim + nt * 128 + tc * 8;
            float4 cd0 = *reinterpret_cast<const float4*>(cur_dist + rb);
            float4 cd1 = *reinterpret_cast<const float4*>(cur_dist + rb + 4);
            float4 nm0 = *reinterpret_cast<const float4*>(ninf + rb);
            float4 nm1 = *reinterpret_cast<const float4*>(ninf + rb + 4);
            float cd[8] = {cd0.x, cd0.y, cd0.z, cd0.w, cd1.x, cd1.y, cd1.z, cd1.w};
            float nm[8] = {nm0.x, nm0.y, nm0.z, nm0.w, nm1.x, nm1.y, nm1.z, nm1.w};
            float e[8];
#pragma unroll
            for (int j = 0; j < 8; j++) {
                float sc = acc[i][j] * (1.0f / SQRT_E_F) - cp * cd[j];
                float lg = CLIP_F * tanhf(sc) + nm[j];
                e[j] = expf(lg);
                rsum[i] += e[j];
            }
            float4 e0 = {e[0], e[1], e[2], e[3]};
            float4 e1 = {e[4], e[5], e[6], e[7]};
            *reinterpret_cast<float4*>(out + rb)     = e0;
            *reinterpret_cast<float4*>(out + rb + 4) = e1;
        }
    }
    // reduce rowsums across the 16 column groups
    __syncthreads();
#pragma unroll
    for (int i = 0; i < 8; i++) Red[tr * 8 + i][tc] = rsum[i];
    __syncthreads();
    if (tid < 64) {
        float s = 0.f;
#pragma unroll
        for (int t = 0; t < 16; t++) s += Red[tid][t];
        g_rowsum[(size_t)b * Pdim + p0 + tid] = s;
    }
}

// ============================================================================
// K5: probs = out / rowsum
// ============================================================================
__global__ void k_norm(float* __restrict__ out)
{
    const size_t total4 = (size_t)Bdim * Pdim * Ndim / 4;
    for (size_t i = (size_t)blockIdx.x * blockDim.x + threadIdx.x; i < total4;
         i += (size_t)gridDim.x * blockDim.x) {
        size_t row = i >> 8;   // N/4 = 256 float4 per row
        float inv = 1.0f / g_rowsum[row];
        float4 v = *reinterpret_cast<const float4*>(out + i * 4);
        v.x *= inv; v.y *= inv; v.z *= inv; v.w *= inv;
        *reinterpret_cast<float4*>(out + i * 4) = v;
    }
}

// ============================================================================
extern "C" void kernel_launch(void* const* d_in, const int* in_sizes, int n_in,
                              void* d_out, int out_size)
{
    const float* enc    = (const float*)d_in[0];
    const float* eq1    = (const float*)d_in[1];
    const float* eq2    = (const float*)d_in[2];
    const float* elast  = (const float*)d_in[3];
    const float* load_  = (const float*)d_in[4];
    const float* left_  = (const float*)d_in[5];
    const float* cdist  = (const float*)d_in[6];
    const float* lscale = (const float*)d_in[7];
    const float* ninf   = (const float*)d_in[8];
    const float* Wq1    = (const float*)d_in[9];
    const float* Wq2    = (const float*)d_in[10];
    const float* Wql    = (const float*)d_in[11];
    const float* Wk     = (const float*)d_in[12];
    const float* Wv     = (const float*)d_in[13];
    const float* aalpha = (const float*)d_in[14];
    const float* palpha = (const float*)d_in[15];
    float* out = (float*)d_out;

    dim3 gkv(Bdim, Ndim / 64);
    k_proj_kv<<<gkv, 256>>>(enc, Wk, Wv);

    dim3 gq(Bdim, Pdim / 64);
    k_proj_q<<<gq, 256>>>(eq1, eq2, elast, Wq1, Wq2, Wql, load_, left_);

    dim3 gaft(Bdim, Pdim / 64);
    k_aft<<<gaft, 256>>>(cdist, ninf, lscale, aalpha);

    k_combine<<<2048, 256>>>();

    dim3 gsc(Bdim, Pdim / 64);
    k_score<<<gsc, 128>>>(enc, cdist, ninf, lscale, palpha, out);

    k_norm<<<4096, 256>>>(out);
}

// round 3
// speedup vs baseline: 1.4333x; 1.4333x over previous
#include <cuda_runtime.h>
#include <cuda_bf16.h>
#include <math.h>
#include <stdint.h>

#define Bdim 32
#define Pdim 1024
#define Ndim 1024
#define Edim 128
#define HQdim 128
#define SQRT_E_F 11.313708498984761f
#define CLIP_F 10.0f

typedef __nv_bfloat16 bf16;

// ---------------- scratch (device globals; no allocations allowed) ----------
__device__ __align__(16) bf16 g_ek_hi [Bdim * (size_t)Ndim * HQdim];
__device__ __align__(16) bf16 g_ek_lo [Bdim * (size_t)Ndim * HQdim];
__device__ __align__(16) bf16 g_ekv_hi[Bdim * (size_t)Ndim * HQdim];
__device__ __align__(16) bf16 g_ekv_lo[Bdim * (size_t)Ndim * HQdim];
__device__ __align__(16) bf16 g_encT_hi[Bdim * (size_t)Edim * Ndim];
__device__ __align__(16) bf16 g_encT_lo[Bdim * (size_t)Edim * Ndim];
__device__ __align__(16) bf16 g_aft_hi[Bdim * (size_t)Pdim * HQdim];
__device__ __align__(16) bf16 g_aft_lo[Bdim * (size_t)Pdim * HQdim];
__device__ __align__(16) float g_sigq[Bdim * (size_t)Pdim * HQdim];

__device__ __forceinline__ float nan2num(float x) {
    if (isnan(x)) return 0.0f;
    if (isinf(x)) return x > 0.0f ? 3.402823466e38f : -3.402823466e38f;
    return x;
}

__device__ __forceinline__ void split_bf(float x, bf16& h, bf16& l) {
    h = __float2bfloat16(x);
    l = __float2bfloat16(x - __bfloat162float(h));
}

__device__ __forceinline__ uint32_t saddr(const void* p) {
    return (uint32_t)__cvta_generic_to_shared(p);
}

__device__ __forceinline__ void ldsm4(uint32_t* r, uint32_t a) {
    asm volatile("ldmatrix.sync.aligned.m8n8.x4.shared.b16 {%0,%1,%2,%3}, [%4];"
                 : "=r"(r[0]), "=r"(r[1]), "=r"(r[2]), "=r"(r[3]) : "r"(a));
}
__device__ __forceinline__ void ldsm4t(uint32_t* r, uint32_t a) {
    asm volatile("ldmatrix.sync.aligned.m8n8.x4.trans.shared.b16 {%0,%1,%2,%3}, [%4];"
                 : "=r"(r[0]), "=r"(r[1]), "=r"(r[2]), "=r"(r[3]) : "r"(a));
}
__device__ __forceinline__ void mma_bf16(float* c, const uint32_t* a, const uint32_t* b) {
    asm volatile(
        "mma.sync.aligned.m16n8k16.row.col.f32.bf16.bf16.f32 "
        "{%0,%1,%2,%3},{%4,%5,%6,%7},{%8,%9},{%0,%1,%2,%3};"
        : "+f"(c[0]), "+f"(c[1]), "+f"(c[2]), "+f"(c[3])
        : "r"(a[0]), "r"(a[1]), "r"(a[2]), "r"(a[3]), "r"(b[0]), "r"(b[1]));
}

// ============================================================================
// K0: transpose enc [B,N,E] -> encT hi/lo bf16 [B,E,N]
// ============================================================================
__global__ __launch_bounds__(256) void k_prep_enc(const float* __restrict__ enc)
{
    __shared__ float tile[32][133];
    const int b = blockIdx.x, n0 = blockIdx.y * 128;
    const int tid = threadIdx.x;

    for (int ec = 0; ec < 4; ec++) {
        const int e0 = ec * 32;
        __syncthreads();
#pragma unroll
        for (int t = 0; t < 4; t++) {
            int i4 = tid + t * 256;
            int r = i4 >> 3, c4 = (i4 & 7) * 4;
            float4 v = *reinterpret_cast<const float4*>(
                enc + ((size_t)b * Ndim + n0 + r) * Edim + e0 + c4);
            tile[c4 + 0][r] = v.x;
            tile[c4 + 1][r] = v.y;
            tile[c4 + 2][r] = v.z;
            tile[c4 + 3][r] = v.w;
        }
        __syncthreads();
#pragma unroll
        for (int t = 0; t < 8; t++) {
            int idx = tid + t * 256;          // 2048 pairs
            int e = idx >> 6;
            int n2 = (idx & 63) * 2;
            float x0 = tile[e][n2], x1 = tile[e][n2 + 1];
            bf16 h0, l0, h1, l1;
            split_bf(x0, h0, l0);
            split_bf(x1, h1, l1);
            size_t g = ((size_t)b * Edim + e0 + e) * Ndim + n0 + n2;
            __nv_bfloat162 hh; hh.x = h0; hh.y = h1;
            __nv_bfloat162 ll; ll.x = l0; ll.y = l1;
            *reinterpret_cast<__nv_bfloat162*>(&g_encT_hi[g]) = hh;
            *reinterpret_cast<__nv_bfloat162*>(&g_encT_lo[g]) = ll;
        }
    }
}

// ============================================================================
// K1: k = enc @ Wk ; v = enc @ Wv ; ek = exp(k) ; ekv = ek*v  (bf16 hi/lo out)
// ============================================================================
__global__ __launch_bounds__(256) void k_proj_kv(
    const float* __restrict__ enc,
    const float* __restrict__ Wk,
    const float* __restrict__ Wv)
{
    const int b  = blockIdx.x;
    const int n0 = blockIdx.y * 64;
    const int tid = threadIdx.x;
    const int tc = tid & 15;
    const int tr = tid >> 4;

    __shared__ float As[16][65];
    __shared__ float WkS[16][128];
    __shared__ float WvS[16][128];

    float accK[4][8], accV[4][8];
#pragma unroll
    for (int i = 0; i < 4; i++)
#pragma unroll
        for (int j = 0; j < 8; j++) { accK[i][j] = 0.f; accV[i][j] = 0.f; }

    const float* Abase = enc + ((size_t)b * Ndim + n0) * Edim;

    for (int k0 = 0; k0 < Edim; k0 += 16) {
        {
            int row = tid >> 2, seg = tid & 3;
            float4 v = *reinterpret_cast<const float4*>(Abase + (size_t)row * Edim + k0 + seg * 4);
            As[seg * 4 + 0][row] = v.x;
            As[seg * 4 + 1][row] = v.y;
            As[seg * 4 + 2][row] = v.z;
            As[seg * 4 + 3][row] = v.w;
        }
#pragma unroll
        for (int i = 0; i < 2; i++) {
            int f = tid + i * 256;
            int e = f >> 5, c4 = f & 31;
            *reinterpret_cast<float4*>(&WkS[e][c4 * 4]) =
                *reinterpret_cast<const float4*>(Wk + (size_t)(k0 + e) * HQdim + c4 * 4);
            *reinterpret_cast<float4*>(&WvS[e][c4 * 4]) =
                *reinterpret_cast<const float4*>(Wv + (size_t)(k0 + e) * HQdim + c4 * 4);
        }
        __syncthreads();
#pragma unroll
        for (int k = 0; k < 16; k++) {
            float a[4];
#pragma unroll
            for (int i = 0; i < 4; i++) a[i] = As[k][tr * 4 + i];
            float4 wk0 = *reinterpret_cast<const float4*>(&WkS[k][tc * 8]);
            float4 wk1 = *reinterpret_cast<const float4*>(&WkS[k][tc * 8 + 4]);
            float4 wv0 = *reinterpret_cast<const float4*>(&WvS[k][tc * 8]);
            float4 wv1 = *reinterpret_cast<const float4*>(&WvS[k][tc * 8 + 4]);
            float wk[8] = {wk0.x, wk0.y, wk0.z, wk0.w, wk1.x, wk1.y, wk1.z, wk1.w};
            float wv[8] = {wv0.x, wv0.y, wv0.z, wv0.w, wv1.x, wv1.y, wv1.z, wv1.w};
#pragma unroll
            for (int i = 0; i < 4; i++)
#pragma unroll
                for (int j = 0; j < 8; j++) {
                    accK[i][j] += a[i] * wk[j];
                    accV[i][j] += a[i] * wv[j];
                }
        }
        __syncthreads();
    }
#pragma unroll
    for (int i = 0; i < 4; i++) {
        int n = n0 + tr * 4 + i;
        size_t base = ((size_t)b * Ndim + n) * HQdim + tc * 8;
        union { bf16 bv[8]; uint4 u; } EH, EL, VH, VL;
#pragma unroll
        for (int j = 0; j < 8; j++) {
            float ek = expf(accK[i][j]);
            float ev = ek * accV[i][j];
            split_bf(ek, EH.bv[j], EL.bv[j]);
            split_bf(ev, VH.bv[j], VL.bv[j]);
        }
        *reinterpret_cast<uint4*>(&g_ek_hi [base]) = EH.u;
        *reinterpret_cast<uint4*>(&g_ek_lo [base]) = EL.u;
        *reinterpret_cast<uint4*>(&g_ekv_hi[base]) = VH.u;
        *reinterpret_cast<uint4*>(&g_ekv_lo[base]) = VL.u;
    }
}

// ============================================================================
// K2: q projections + sigmoid  (fp32)
// ============================================================================
__global__ __launch_bounds__(256) void k_proj_q(
    const float* __restrict__ eq1,
    const float* __restrict__ eq2,
    const float* __restrict__ elast,
    const float* __restrict__ Wq1,
    const float* __restrict__ Wq2,
    const float* __restrict__ Wql,
    const float* __restrict__ load_,
    const float* __restrict__ left_)
{
    const int b  = blockIdx.x;
    const int p0 = blockIdx.y * 64;
    const int tid = threadIdx.x;
    const int tc = tid & 15;
    const int tr = tid >> 4;

    __shared__ float As[16][65];
    __shared__ float Ws[16][128];

    float acc[4][8];
#pragma unroll
    for (int i = 0; i < 4; i++)
#pragma unroll
        for (int j = 0; j < 8; j++) acc[i][j] = 0.f;

    const float* Aptr[3] = {eq1, eq2, elast};
    const float* Wptr[3] = {Wq1, Wq2, Wql};

    for (int m = 0; m < 3; m++) {
        const float* Ab = Aptr[m] + ((size_t)b * Pdim + p0) * Edim;
        const float* Wb = Wptr[m];
        for (int k0 = 0; k0 < Edim; k0 += 16) {
            {
                int row = tid >> 2, seg = tid & 3;
                float4 v = *reinterpret_cast<const float4*>(Ab + (size_t)row * Edim + k0 + seg * 4);
                As[seg * 4 + 0][row] = v.x;
                As[seg * 4 + 1][row] = v.y;
                As[seg * 4 + 2][row] = v.z;
                As[seg * 4 + 3][row] = v.w;
            }
#pragma unroll
            for (int i = 0; i < 2; i++) {
                int f = tid + i * 256;
                int e = f >> 5, c4 = f & 31;
                *reinterpret_cast<float4*>(&Ws[e][c4 * 4]) =
                    *reinterpret_cast<const float4*>(Wb + (size_t)(k0 + e) * HQdim + c4 * 4);
            }
            __syncthreads();
#pragma unroll
            for (int k = 0; k < 16; k++) {
                float a[4];
#pragma unroll
                for (int i = 0; i < 4; i++) a[i] = As[k][tr * 4 + i];
                float4 w0 = *reinterpret_cast<const float4*>(&Ws[k][tc * 8]);
                float4 w1 = *reinterpret_cast<const float4*>(&Ws[k][tc * 8 + 4]);
                float w[8] = {w0.x, w0.y, w0.z, w0.w, w1.x, w1.y, w1.z, w1.w};
#pragma unroll
                for (int i = 0; i < 4; i++)
#pragma unroll
                    for (int j = 0; j < 8; j++) acc[i][j] += a[i] * w[j];
            }
            __syncthreads();
        }
    }
    int d0 = tc * 8;
    float wl[8], wr[8];
#pragma unroll
    for (int j = 0; j < 8; j++) {
        wl[j] = Wql[(size_t)128 * HQdim + d0 + j];
        wr[j] = Wql[(size_t)129 * HQdim + d0 + j];
    }
#pragma unroll
    for (int i = 0; i < 4; i++) {
        int p = p0 + tr * 4 + i;
        float lo = load_[(size_t)b * Pdim + p];
        float le = left_[(size_t)b * Pdim + p];
        float s[8];
#pragma unroll
        for (int j = 0; j < 8; j++) {
            float q = acc[i][j] + lo * wl[j] + le * wr[j];
            s[j] = 1.0f / (1.0f + expf(-q));
        }
        size_t base = ((size_t)b * Pdim + p) * HQdim + d0;
        float4 s0 = {s[0], s[1], s[2], s[3]};
        float4 s1 = {s[4], s[5], s[6], s[7]};
        *reinterpret_cast<float4*>(&g_sigq[base])     = s0;
        *reinterpret_cast<float4*>(&g_sigq[base + 4]) = s1;
    }
}

// ============================================================================
// K3: bf16x3 tensor-core AFT. block tile 128(m) x 256(n: num|den), K = 1024.
// A = exp(nm - c2*cd) computed on the fly + split; B = [ekv|ek] hi/lo.
// Epilogue: AFT_out = sigq * n2n(num)/(n2n(den)+1e-20), split -> g_aft hi/lo.
// 8 warps (2x4), warp tile 64x64.  Dynamic smem (union w/ den exchange buf).
// ============================================================================
#define AFT_SA 40      // A row stride (bf16), 32 + 8
#define AFT_SB 264     // B row stride (bf16), 256 + 8
#define AFT_SMEM_BYTES 69632

__global__ __launch_bounds__(256, 1) void k_aft_mma(
    const float* __restrict__ cur_dist,
    const float* __restrict__ ninf,
    const float* __restrict__ ls,
    const float* __restrict__ aalpha)
{
    extern __shared__ __align__(16) char sm_raw[];
    bf16* A_hi = reinterpret_cast<bf16*>(sm_raw);          // 128*40  = 5120
    bf16* A_lo = A_hi + 128 * AFT_SA;
    bf16* B_hi = A_lo + 128 * AFT_SA;                      // 32*264  = 8448
    bf16* B_lo = B_hi + 32 * AFT_SB;
    float* den_s = reinterpret_cast<float*>(sm_raw);       // union: 128*132 floats

    const int b  = blockIdx.x;
    const int p0 = blockIdx.y * 128;
    const int tid = threadIdx.x;
    const int l   = tid & 31;
    const int wid = tid >> 5;
    const int wm  = wid >> 2;     // 0..1
    const int wn  = wid & 3;      // 0..3
    const float c2 = ls[0] * aalpha[0];

    float C[4][8][4];
#pragma unroll
    for (int i = 0; i < 4; i++)
#pragma unroll
        for (int j = 0; j < 8; j++)
#pragma unroll
            for (int r = 0; r < 4; r++) C[i][j][r] = 0.f;

    for (int nc = 0; nc < 32; nc++) {
        const int n0 = nc * 32;
        __syncthreads();
        // ---- A fill: 128 x 32, exp(nm - c2*cd), split hi/lo
#pragma unroll
        for (int t = 0; t < 4; t++) {
            int i4 = tid + t * 256;
            int r = i4 >> 3, c4 = (i4 & 7) * 4;
            size_t g = ((size_t)b * Pdim + p0 + r) * Ndim + n0 + c4;
            float4 cd = *reinterpret_cast<const float4*>(cur_dist + g);
            float4 nm = *reinterpret_cast<const float4*>(ninf + g);
            float e0 = expf(nm.x - c2 * cd.x);
            float e1 = expf(nm.y - c2 * cd.y);
            float e2 = expf(nm.z - c2 * cd.z);
            float e3 = expf(nm.w - c2 * cd.w);
            union { bf16 bv[4]; uint2 u; } H, L;
            split_bf(e0, H.bv[0], L.bv[0]);
            split_bf(e1, H.bv[1], L.bv[1]);
            split_bf(e2, H.bv[2], L.bv[2]);
            split_bf(e3, H.bv[3], L.bv[3]);
            *reinterpret_cast<uint2*>(&A_hi[r * AFT_SA + c4]) = H.u;
            *reinterpret_cast<uint2*>(&A_lo[r * AFT_SA + c4]) = L.u;
        }
        // ---- B fill: 32 x 256 (cols 0..127 ekv, 128..255 ek), hi & lo
#pragma unroll
        for (int t = 0; t < 4; t++) {
            int i8 = tid + t * 256;
            int r = i8 >> 5, c8 = (i8 & 31) * 8;
            size_t gb = ((size_t)b * Ndim + n0 + r) * HQdim + (c8 < 128 ? c8 : c8 - 128);
            const bf16* sh = (c8 < 128) ? (g_ekv_hi + gb) : (g_ek_hi + gb);
            const bf16* sl = (c8 < 128) ? (g_ekv_lo + gb) : (g_ek_lo + gb);
            *reinterpret_cast<uint4*>(&B_hi[r * AFT_SB + c8]) = *reinterpret_cast<const uint4*>(sh);
            *reinterpret_cast<uint4*>(&B_lo[r * AFT_SB + c8]) = *reinterpret_cast<const uint4*>(sl);
        }
        __syncthreads();
        // ---- mma over two k16 steps
#pragma unroll
        for (int kk = 0; kk < 2; kk++) {
            uint32_t ah[4][4], al[4][4];
            const int arow = l & 15;
            const int acol = kk * 16 + ((l >> 1) & 8);
#pragma unroll
            for (int i = 0; i < 4; i++) {
                ldsm4(ah[i], saddr(&A_hi[(wm * 64 + i * 16 + arow) * AFT_SA + acol]));
                ldsm4(al[i], saddr(&A_lo[(wm * 64 + i * 16 + arow) * AFT_SA + acol]));
            }
            const int brow = kk * 16 + (l & 15);
#pragma unroll
            for (int j = 0; j < 4; j++) {
                uint32_t bh[4], bl[4];
                const int bcol = wn * 64 + j * 16 + ((l >> 1) & 8);
                ldsm4t(bh, saddr(&B_hi[brow * AFT_SB + bcol]));
                ldsm4t(bl, saddr(&B_lo[brow * AFT_SB + bcol]));
#pragma unroll
                for (int i = 0; i < 4; i++) {
                    mma_bf16(C[i][2 * j],     ah[i], bh);
                    mma_bf16(C[i][2 * j],     al[i], bh);
                    mma_bf16(C[i][2 * j],     ah[i], bl);
                    mma_bf16(C[i][2 * j + 1], ah[i], bh + 2);
                    mma_bf16(C[i][2 * j + 1], al[i], bh + 2);
                    mma_bf16(C[i][2 * j + 1], ah[i], bl + 2);
                }
            }
        }
    }
    // ---- epilogue: den warps stage to smem, num warps combine
    __syncthreads();
    const int qr = l >> 2, qc = (l & 3) * 2;
    if (wn >= 2) {
        const int dbase = (wn - 2) * 64;
#pragma unroll
        for (int i = 0; i < 4; i++) {
            int r0 = wm * 64 + i * 16 + qr;
#pragma unroll
            for (int j = 0; j < 8; j++) {
                int d = dbase + j * 8 + qc;
                den_s[r0 * 132 + d]           = C[i][j][0];
                den_s[r0 * 132 + d + 1]       = C[i][j][1];
                den_s[(r0 + 8) * 132 + d]     = C[i][j][2];
                den_s[(r0 + 8) * 132 + d + 1] = C[i][j][3];
            }
        }
    }
    __syncthreads();
    if (wn < 2) {
        const int dbase = wn * 64;
#pragma unroll
        for (int i = 0; i < 4; i++) {
#pragma unroll
            for (int h = 0; h < 2; h++) {
                int r = wm * 64 + i * 16 + qr + h * 8;
                size_t sb = ((size_t)b * Pdim + p0 + r) * HQdim;
#pragma unroll
                for (int j = 0; j < 8; j++) {
                    int d = dbase + j * 8 + qc;
                    float nu0 = C[i][j][2 * h], nu1 = C[i][j][2 * h + 1];
                    float de0 = den_s[r * 132 + d], de1 = den_s[r * 132 + d + 1];
                    float2 sg = *reinterpret_cast<const float2*>(g_sigq + sb + d);
                    float a0 = sg.x * nan2num(nu0) / (nan2num(de0) + 1e-20f);
                    float a1 = sg.y * nan2num(nu1) / (nan2num(de1) + 1e-20f);
                    bf16 h0, l0, h1, l1;
                    split_bf(a0, h0, l0);
                    split_bf(a1, h1, l1);
                    __nv_bfloat162 hh; hh.x = h0; hh.y = h1;
                    __nv_bfloat162 ll; ll.x = l0; ll.y = l1;
                    *reinterpret_cast<__nv_bfloat162*>(&g_aft_hi[sb + d]) = hh;
                    *reinterpret_cast<__nv_bfloat162*>(&g_aft_lo[sb + d]) = ll;
                }
            }
        }
    }
}

// ============================================================================
// K4: bf16x3 tensor-core score GEMM + fused tanh-clip softmax (full row per
// block -> block-local rowsum -> in-kernel normalization via L2 re-read).
// block tile 128(m) x 128(n per nt, 8 nt), K=128 in chunks of 32.
// 8 warps (2x4), warp tile 64x32.
// ============================================================================
#define SC_SA 40
#define SC_SB 136

__global__ __launch_bounds__(256, 1) void k_score_mma(
    const float* __restrict__ cur_dist,
    const float* __restrict__ ninf,
    const float* __restrict__ ls,
    const float* __restrict__ palpha,
    float* __restrict__ out)
{
    __shared__ __align__(16) bf16 A_hi[128 * SC_SA];
    __shared__ __align__(16) bf16 A_lo[128 * SC_SA];
    __shared__ __align__(16) bf16 B_hi[32 * SC_SB];
    __shared__ __align__(16) bf16 B_lo[32 * SC_SB];
    __shared__ float partial[128 * 4];
    __shared__ float inv_s[128];

    const int b  = blockIdx.x;
    const int p0 = blockIdx.y * 128;
    const int tid = threadIdx.x;
    const int l   = tid & 31;
    const int wid = tid >> 5;
    const int wm  = wid >> 2;     // 0..1
    const int wn  = wid & 3;      // 0..3
    const float cp = ls[0] * palpha[0];
    const float inv_se = 1.0f / SQRT_E_F;
    const int qr = l >> 2, qc = (l & 3) * 2;

    float rs[4][2];
#pragma unroll
    for (int i = 0; i < 4; i++) { rs[i][0] = 0.f; rs[i][1] = 0.f; }

    for (int nt = 0; nt < 8; nt++) {
        float C[4][4][4];
#pragma unroll
        for (int i = 0; i < 4; i++)
#pragma unroll
            for (int j = 0; j < 4; j++)
#pragma unroll
                for (int r = 0; r < 4; r++) C[i][j][r] = 0.f;

        for (int kc = 0; kc < 4; kc++) {
            __syncthreads();
            // A fill: 128 x 32 bf16 (hi/lo) from g_aft
#pragma unroll
            for (int t = 0; t < 2; t++) {
                int i4 = tid + t * 256;
                int r = i4 >> 2, c8 = (i4 & 3) * 8;
                size_t g = ((size_t)b * Pdim + p0 + r) * HQdim + kc * 32 + c8;
                *reinterpret_cast<uint4*>(&A_hi[r * SC_SA + c8]) =
                    *reinterpret_cast<const uint4*>(&g_aft_hi[g]);
                *reinterpret_cast<uint4*>(&A_lo[r * SC_SA + c8]) =
                    *reinterpret_cast<const uint4*>(&g_aft_lo[g]);
            }
            // B fill: 32 x 128 from g_encT
#pragma unroll
            for (int t = 0; t < 2; t++) {
                int i4 = tid + t * 256;
                int r = i4 >> 4, c8 = (i4 & 15) * 8;
                size_t g = ((size_t)b * Edim + kc * 32 + r) * Ndim + nt * 128 + c8;
                *reinterpret_cast<uint4*>(&B_hi[r * SC_SB + c8]) =
                    *reinterpret_cast<const uint4*>(&g_encT_hi[g]);
                *reinterpret_cast<uint4*>(&B_lo[r * SC_SB + c8]) =
                    *reinterpret_cast<const uint4*>(&g_encT_lo[g]);
            }
            __syncthreads();
#pragma unroll
            for (int kk = 0; kk < 2; kk++) {
                uint32_t ah[4][4], al[4][4];
                const int arow = l & 15;
                const int acol = kk * 16 + ((l >> 1) & 8);
#pragma unroll
                for (int i = 0; i < 4; i++) {
                    ldsm4(ah[i], saddr(&A_hi[(wm * 64 + i * 16 + arow) * SC_SA + acol]));
                    ldsm4(al[i], saddr(&A_lo[(wm * 64 + i * 16 + arow) * SC_SA + acol]));
                }
                const int brow = kk * 16 + (l & 15);
#pragma unroll
                for (int j2 = 0; j2 < 2; j2++) {
                    uint32_t bh[4], bl[4];
                    const int bcol = wn * 32 + j2 * 16 + ((l >> 1) & 8);
                    ldsm4t(bh, saddr(&B_hi[brow * SC_SB + bcol]));
                    ldsm4t(bl, saddr(&B_lo[brow * SC_SB + bcol]));
#pragma unroll
                    for (int i = 0; i < 4; i++) {
                        mma_bf16(C[i][2 * j2],     ah[i], bh);
                        mma_bf16(C[i][2 * j2],     al[i], bh);
                        mma_bf16(C[i][2 * j2],     ah[i], bl);
                        mma_bf16(C[i][2 * j2 + 1], ah[i], bh + 2);
                        mma_bf16(C[i][2 * j2 + 1], al[i], bh + 2);
                        mma_bf16(C[i][2 * j2 + 1], ah[i], bl + 2);
                    }
                }
            }
        }
        // epilogue for this n-tile: logits -> exp, accumulate row sums
#pragma unroll
        for (int i = 0; i < 4; i++) {
            int r = wm * 64 + i * 16 + qr;
#pragma unroll
            for (int j = 0; j < 4; j++) {
                int n = nt * 128 + wn * 32 + j * 8 + qc;
                size_t g0 = ((size_t)b * Pdim + p0 + r) * Ndim + n;
                size_t g1 = g0 + (size_t)8 * Ndim;
                float2 cd0 = *reinterpret_cast<const float2*>(cur_dist + g0);
                float2 nm0 = *reinterpret_cast<const float2*>(ninf + g0);
                float2 cd1 = *reinterpret_cast<const float2*>(cur_dist + g1);
                float2 nm1 = *reinterpret_cast<const float2*>(ninf + g1);
                float e00 = expf(CLIP_F * tanhf(C[i][j][0] * inv_se - cp * cd0.x) + nm0.x);
                float e01 = expf(CLIP_F * tanhf(C[i][j][1] * inv_se - cp * cd0.y) + nm0.y);
                float e10 = expf(CLIP_F * tanhf(C[i][j][2] * inv_se - cp * cd1.x) + nm1.x);
                float e11 = expf(CLIP_F * tanhf(C[i][j][3] * inv_se - cp * cd1.y) + nm1.y);
                float2 o0 = {e00, e01};
                float2 o1 = {e10, e11};
                *reinterpret_cast<float2*>(out + g0) = o0;
                *reinterpret_cast<float2*>(out + g1) = o1;
                rs[i][0] += e00 + e01;
                rs[i][1] += e10 + e11;
            }
        }
    }
    // reduce rowsums: over lane quad, then across wn warps via smem
#pragma unroll
    for (int i = 0; i < 4; i++)
#pragma unroll
        for (int h = 0; h < 2; h++) {
            float v = rs[i][h];
            v += __shfl_xor_sync(0xffffffffu, v, 1);
            v += __shfl_xor_sync(0xffffffffu, v, 2);
            rs[i][h] = v;
        }
    if ((l & 3) == 0) {
#pragma unroll
        for (int i = 0; i < 4; i++) {
            partial[(wm * 64 + i * 16 + (l >> 2)) * 4 + wn]     = rs[i][0];
            partial[(wm * 64 + i * 16 + (l >> 2) + 8) * 4 + wn] = rs[i][1];
        }
    }
    __syncthreads();   // also makes all out writes visible block-wide
    if (tid < 128) {
        float s = partial[tid * 4] + partial[tid * 4 + 1] +
                  partial[tid * 4 + 2] + partial[tid * 4 + 3];
        inv_s[tid] = 1.0f / s;
    }
    __syncthreads();
    // normalize (L2-hot re-read of this block's region)
    const size_t obase4 = (((size_t)b * Pdim + p0) * Ndim) >> 2;
    float4* out4 = reinterpret_cast<float4*>(out);
#pragma unroll 4
    for (int t = 0; t < 128; t++) {
        int i4 = tid + t * 256;
        int r = i4 >> 8;
        float4 v = __ldcg(out4 + obase4 + i4);
        float s = inv_s[r];
        v.x *= s; v.y *= s; v.z *= s; v.w *= s;
        out4[obase4 + i4] = v;
    }
}

// ============================================================================
extern "C" void kernel_launch(void* const* d_in, const int* in_sizes, int n_in,
                              void* d_out, int out_size)
{
    const float* enc    = (const float*)d_in[0];
    const float* eq1    = (const float*)d_in[1];
    const float* eq2    = (const float*)d_in[2];
    const float* elast  = (const float*)d_in[3];
    const float* load_  = (const float*)d_in[4];
    const float* left_  = (const float*)d_in[5];
    const float* cdist  = (const float*)d_in[6];
    const float* lscale = (const float*)d_in[7];
    const float* ninf   = (const float*)d_in[8];
    const float* Wq1    = (const float*)d_in[9];
    const float* Wq2    = (const float*)d_in[10];
    const float* Wql    = (const float*)d_in[11];
    const float* Wk     = (const float*)d_in[12];
    const float* Wv     = (const float*)d_in[13];
    const float* aalpha = (const float*)d_in[14];
    const float* palpha = (const float*)d_in[15];
    float* out = (float*)d_out;

    cudaFuncSetAttribute(k_aft_mma, cudaFuncAttributeMaxDynamicSharedMemorySize,
                         AFT_SMEM_BYTES);

    k_prep_enc<<<dim3(Bdim, Ndim / 128), 256>>>(enc);
    k_proj_kv<<<dim3(Bdim, Ndim / 64), 256>>>(enc, Wk, Wv);
    k_proj_q<<<dim3(Bdim, Pdim / 64), 256>>>(eq1, eq2, elast, Wq1, Wq2, Wql, load_, left_);
    k_aft_mma<<<dim3(Bdim, Pdim / 128), 256, AFT_SMEM_BYTES>>>(cdist, ninf, lscale, aalpha);
    k_score_mma<<<dim3(Bdim, Pdim / 128), 256>>>(cdist, ninf, lscale, palpha, out);
}

// round 4
// speedup vs baseline: 1.7781x; 1.2406x over previous
#include <cuda_runtime.h>
#include <cuda_bf16.h>
#include <math.h>
#include <stdint.h>

#define Bdim 32
#define Pdim 1024
#define Ndim 1024
#define Edim 128
#define HQdim 128
#define SQRT_E_F 11.313708498984761f
#define CLIP_F 10.0f

typedef __nv_bfloat16 bf16;

// ---------------- scratch (device globals; no allocations allowed) ----------
__device__ __align__(16) bf16 g_ek_hi [Bdim * (size_t)Ndim * HQdim];
__device__ __align__(16) bf16 g_ek_lo [Bdim * (size_t)Ndim * HQdim];
__device__ __align__(16) bf16 g_ekv_hi[Bdim * (size_t)Ndim * HQdim];
__device__ __align__(16) bf16 g_ekv_lo[Bdim * (size_t)Ndim * HQdim];
__device__ __align__(16) bf16 g_encT_hi[Bdim * (size_t)Edim * Ndim];
__device__ __align__(16) bf16 g_encT_lo[Bdim * (size_t)Edim * Ndim];
__device__ __align__(16) bf16 g_aft_hi[Bdim * (size_t)Pdim * HQdim];
__device__ __align__(16) bf16 g_aft_lo[Bdim * (size_t)Pdim * HQdim];
__device__ __align__(16) float g_sigq[Bdim * (size_t)Pdim * HQdim];

__device__ __forceinline__ float nan2num(float x) {
    if (isnan(x)) return 0.0f;
    if (isinf(x)) return x > 0.0f ? 3.402823466e38f : -3.402823466e38f;
    return x;
}

__device__ __forceinline__ void split_bf(float x, bf16& h, bf16& l) {
    h = __float2bfloat16(x);
    l = __float2bfloat16(x - __bfloat162float(h));
}

__device__ __forceinline__ uint32_t saddr(const void* p) {
    return (uint32_t)__cvta_generic_to_shared(p);
}

__device__ __forceinline__ void cpa16(uint32_t s, const void* g) {
    asm volatile("cp.async.cg.shared.global [%0], [%1], 16;" :: "r"(s), "l"(g));
}
#define CPA_COMMIT asm volatile("cp.async.commit_group;")
#define CPA_WAIT0  asm volatile("cp.async.wait_group 0;")

__device__ __forceinline__ void ldsm4(uint32_t* r, uint32_t a) {
    asm volatile("ldmatrix.sync.aligned.m8n8.x4.shared.b16 {%0,%1,%2,%3}, [%4];"
                 : "=r"(r[0]), "=r"(r[1]), "=r"(r[2]), "=r"(r[3]) : "r"(a));
}
__device__ __forceinline__ void ldsm4t(uint32_t* r, uint32_t a) {
    asm volatile("ldmatrix.sync.aligned.m8n8.x4.trans.shared.b16 {%0,%1,%2,%3}, [%4];"
                 : "=r"(r[0]), "=r"(r[1]), "=r"(r[2]), "=r"(r[3]) : "r"(a));
}
__device__ __forceinline__ void mma_bf16(float* c, const uint32_t* a, const uint32_t* b) {
    asm volatile(
        "mma.sync.aligned.m16n8k16.row.col.f32.bf16.bf16.f32 "
        "{%0,%1,%2,%3},{%4,%5,%6,%7},{%8,%9},{%0,%1,%2,%3};"
        : "+f"(c[0]), "+f"(c[1]), "+f"(c[2]), "+f"(c[3])
        : "r"(a[0]), "r"(a[1]), "r"(a[2]), "r"(a[3]), "r"(b[0]), "r"(b[1]));
}

// ============================================================================
// K0: transpose enc [B,N,E] -> encT hi/lo bf16 [B,E,N]
// ============================================================================
__global__ __launch_bounds__(256) void k_prep_enc(const float* __restrict__ enc)
{
    __shared__ float tile[32][133];
    const int b = blockIdx.x, n0 = blockIdx.y * 128;
    const int tid = threadIdx.x;

    for (int ec = 0; ec < 4; ec++) {
        const int e0 = ec * 32;
        __syncthreads();
#pragma unroll
        for (int t = 0; t < 4; t++) {
            int i4 = tid + t * 256;
            int r = i4 >> 3, c4 = (i4 & 7) * 4;
            float4 v = *reinterpret_cast<const float4*>(
                enc + ((size_t)b * Ndim + n0 + r) * Edim + e0 + c4);
            tile[c4 + 0][r] = v.x;
            tile[c4 + 1][r] = v.y;
            tile[c4 + 2][r] = v.z;
            tile[c4 + 3][r] = v.w;
        }
        __syncthreads();
#pragma unroll
        for (int t = 0; t < 8; t++) {
            int idx = tid + t * 256;
            int e = idx >> 6;
            int n2 = (idx & 63) * 2;
            float x0 = tile[e][n2], x1 = tile[e][n2 + 1];
            bf16 h0, l0, h1, l1;
            split_bf(x0, h0, l0);
            split_bf(x1, h1, l1);
            size_t g = ((size_t)b * Edim + e0 + e) * Ndim + n0 + n2;
            __nv_bfloat162 hh; hh.x = h0; hh.y = h1;
            __nv_bfloat162 ll; ll.x = l0; ll.y = l1;
            *reinterpret_cast<__nv_bfloat162*>(&g_encT_hi[g]) = hh;
            *reinterpret_cast<__nv_bfloat162*>(&g_encT_lo[g]) = ll;
        }
    }
}

// ============================================================================
// K1: k = enc @ Wk ; v = enc @ Wv ; ek = exp(k) ; ekv = ek*v  (bf16 hi/lo out)
// ============================================================================
__global__ __launch_bounds__(256) void k_proj_kv(
    const float* __restrict__ enc,
    const float* __restrict__ Wk,
    const float* __restrict__ Wv)
{
    const int b  = blockIdx.x;
    const int n0 = blockIdx.y * 64;
    const int tid = threadIdx.x;
    const int tc = tid & 15;
    const int tr = tid >> 4;

    __shared__ float As[16][65];
    __shared__ float WkS[16][128];
    __shared__ float WvS[16][128];

    float accK[4][8], accV[4][8];
#pragma unroll
    for (int i = 0; i < 4; i++)
#pragma unroll
        for (int j = 0; j < 8; j++) { accK[i][j] = 0.f; accV[i][j] = 0.f; }

    const float* Abase = enc + ((size_t)b * Ndim + n0) * Edim;

    for (int k0 = 0; k0 < Edim; k0 += 16) {
        {
            int row = tid >> 2, seg = tid & 3;
            float4 v = *reinterpret_cast<const float4*>(Abase + (size_t)row * Edim + k0 + seg * 4);
            As[seg * 4 + 0][row] = v.x;
            As[seg * 4 + 1][row] = v.y;
            As[seg * 4 + 2][row] = v.z;
            As[seg * 4 + 3][row] = v.w;
        }
#pragma unroll
        for (int i = 0; i < 2; i++) {
            int f = tid + i * 256;
            int e = f >> 5, c4 = f & 31;
            *reinterpret_cast<float4*>(&WkS[e][c4 * 4]) =
                *reinterpret_cast<const float4*>(Wk + (size_t)(k0 + e) * HQdim + c4 * 4);
            *reinterpret_cast<float4*>(&WvS[e][c4 * 4]) =
                *reinterpret_cast<const float4*>(Wv + (size_t)(k0 + e) * HQdim + c4 * 4);
        }
        __syncthreads();
#pragma unroll
        for (int k = 0; k < 16; k++) {
            float a[4];
#pragma unroll
            for (int i = 0; i < 4; i++) a[i] = As[k][tr * 4 + i];
            float4 wk0 = *reinterpret_cast<const float4*>(&WkS[k][tc * 8]);
            float4 wk1 = *reinterpret_cast<const float4*>(&WkS[k][tc * 8 + 4]);
            float4 wv0 = *reinterpret_cast<const float4*>(&WvS[k][tc * 8]);
            float4 wv1 = *reinterpret_cast<const float4*>(&WvS[k][tc * 8 + 4]);
            float wk[8] = {wk0.x, wk0.y, wk0.z, wk0.w, wk1.x, wk1.y, wk1.z, wk1.w};
            float wv[8] = {wv0.x, wv0.y, wv0.z, wv0.w, wv1.x, wv1.y, wv1.z, wv1.w};
#pragma unroll
            for (int i = 0; i < 4; i++)
#pragma unroll
                for (int j = 0; j < 8; j++) {
                    accK[i][j] += a[i] * wk[j];
                    accV[i][j] += a[i] * wv[j];
                }
        }
        __syncthreads();
    }
#pragma unroll
    for (int i = 0; i < 4; i++) {
        int n = n0 + tr * 4 + i;
        size_t base = ((size_t)b * Ndim + n) * HQdim + tc * 8;
        union { bf16 bv[8]; uint4 u; } EH, EL, VH, VL;
#pragma unroll
        for (int j = 0; j < 8; j++) {
            float ek = expf(accK[i][j]);
            float ev = ek * accV[i][j];
            split_bf(ek, EH.bv[j], EL.bv[j]);
            split_bf(ev, VH.bv[j], VL.bv[j]);
        }
        *reinterpret_cast<uint4*>(&g_ek_hi [base]) = EH.u;
        *reinterpret_cast<uint4*>(&g_ek_lo [base]) = EL.u;
        *reinterpret_cast<uint4*>(&g_ekv_hi[base]) = VH.u;
        *reinterpret_cast<uint4*>(&g_ekv_lo[base]) = VL.u;
    }
}

// ============================================================================
// K2: q projections + sigmoid  (fp32)
// ============================================================================
__global__ __launch_bounds__(256) void k_proj_q(
    const float* __restrict__ eq1,
    const float* __restrict__ eq2,
    const float* __restrict__ elast,
    const float* __restrict__ Wq1,
    const float* __restrict__ Wq2,
    const float* __restrict__ Wql,
    const float* __restrict__ load_,
    const float* __restrict__ left_)
{
    const int b  = blockIdx.x;
    const int p0 = blockIdx.y * 64;
    const int tid = threadIdx.x;
    const int tc = tid & 15;
    const int tr = tid >> 4;

    __shared__ float As[16][65];
    __shared__ float Ws[16][128];

    float acc[4][8];
#pragma unroll
    for (int i = 0; i < 4; i++)
#pragma unroll
        for (int j = 0; j < 8; j++) acc[i][j] = 0.f;

    const float* Aptr[3] = {eq1, eq2, elast};
    const float* Wptr[3] = {Wq1, Wq2, Wql};

    for (int m = 0; m < 3; m++) {
        const float* Ab = Aptr[m] + ((size_t)b * Pdim + p0) * Edim;
        const float* Wb = Wptr[m];
        for (int k0 = 0; k0 < Edim; k0 += 16) {
            {
                int row = tid >> 2, seg = tid & 3;
                float4 v = *reinterpret_cast<const float4*>(Ab + (size_t)row * Edim + k0 + seg * 4);
                As[seg * 4 + 0][row] = v.x;
                As[seg * 4 + 1][row] = v.y;
                As[seg * 4 + 2][row] = v.z;
                As[seg * 4 + 3][row] = v.w;
            }
#pragma unroll
            for (int i = 0; i < 2; i++) {
                int f = tid + i * 256;
                int e = f >> 5, c4 = f & 31;
                *reinterpret_cast<float4*>(&Ws[e][c4 * 4]) =
                    *reinterpret_cast<const float4*>(Wb + (size_t)(k0 + e) * HQdim + c4 * 4);
            }
            __syncthreads();
#pragma unroll
            for (int k = 0; k < 16; k++) {
                float a[4];
#pragma unroll
                for (int i = 0; i < 4; i++) a[i] = As[k][tr * 4 + i];
                float4 w0 = *reinterpret_cast<const float4*>(&Ws[k][tc * 8]);
                float4 w1 = *reinterpret_cast<const float4*>(&Ws[k][tc * 8 + 4]);
                float w[8] = {w0.x, w0.y, w0.z, w0.w, w1.x, w1.y, w1.z, w1.w};
#pragma unroll
                for (int i = 0; i < 4; i++)
#pragma unroll
                    for (int j = 0; j < 8; j++) acc[i][j] += a[i] * w[j];
            }
            __syncthreads();
        }
    }
    int d0 = tc * 8;
    float wl[8], wr[8];
#pragma unroll
    for (int j = 0; j < 8; j++) {
        wl[j] = Wql[(size_t)128 * HQdim + d0 + j];
        wr[j] = Wql[(size_t)129 * HQdim + d0 + j];
    }
#pragma unroll
    for (int i = 0; i < 4; i++) {
        int p = p0 + tr * 4 + i;
        float lo = load_[(size_t)b * Pdim + p];
        float le = left_[(size_t)b * Pdim + p];
        float s[8];
#pragma unroll
        for (int j = 0; j < 8; j++) {
            float q = acc[i][j] + lo * wl[j] + le * wr[j];
            s[j] = 1.0f / (1.0f + expf(-q));
        }
        size_t base = ((size_t)b * Pdim + p) * HQdim + d0;
        float4 s0 = {s[0], s[1], s[2], s[3]};
        float4 s1 = {s[4], s[5], s[6], s[7]};
        *reinterpret_cast<float4*>(&g_sigq[base])     = s0;
        *reinterpret_cast<float4*>(&g_sigq[base + 4]) = s1;
    }
}

// ============================================================================
// K3: bf16x3 AFT, 512 threads / 16 warps, warp tile 32x64, double-buffered
// smem, cp.async B fills, software-pipelined computed A tile.
// ============================================================================
#define AFT_SA 40
#define AFT_SB 264
#define AFT_A_ELEMS (128 * AFT_SA)               // per buffer
#define AFT_B_ELEMS (32 * AFT_SB)
#define AFT_SMEM_BYTES ((2 * AFT_A_ELEMS * 2 + 2 * AFT_B_ELEMS * 2) * 2)  // 108544

__global__ __launch_bounds__(512, 1) void k_aft_mma(
    const float* __restrict__ cur_dist,
    const float* __restrict__ ninf,
    const float* __restrict__ ls,
    const float* __restrict__ aalpha)
{
    extern __shared__ __align__(16) char sm_raw[];
    bf16* A_hi = reinterpret_cast<bf16*>(sm_raw);            // [2][128*40]
    bf16* A_lo = A_hi + 2 * AFT_A_ELEMS;
    bf16* B_hi = A_lo + 2 * AFT_A_ELEMS;                     // [2][32*264]
    bf16* B_lo = B_hi + 2 * AFT_B_ELEMS;
    float* den_s = reinterpret_cast<float*>(sm_raw);         // union (epilogue only)

    const int b  = blockIdx.x;
    const int p0 = blockIdx.y * 128;
    const int tid = threadIdx.x;
    const int l   = tid & 31;
    const int wid = tid >> 5;
    const int wm  = wid >> 2;     // 0..3 (32-row tiles)
    const int wn  = wid & 3;      // 0..3 (64-col tiles)
    const float c2 = ls[0] * aalpha[0];

    // A-fill thread mapping: 1024 float4 slots (128 rows x 8 groups)
    const int fa_r0 = tid >> 3,            fa_c0 = (tid & 7) * 4;
    const int fa_r1 = (tid + 512) >> 3,    fa_c1 = ((tid + 512) & 7) * 4;
    // B-fill: 1024 uint4 slots (32 rows x 32 groups)
    const int fb_r0 = tid >> 5,            fb_c0 = (tid & 31) * 8;
    const int fb_r1 = (tid + 512) >> 5,    fb_c1 = ((tid + 512) & 31) * 8;

    float C[2][8][4];
#pragma unroll
    for (int i = 0; i < 2; i++)
#pragma unroll
        for (int j = 0; j < 8; j++)
#pragma unroll
            for (int r = 0; r < 4; r++) C[i][j][r] = 0.f;

    float4 pf_cd[2], pf_nm[2];

    // ---- helpers as lambdas
    auto issueB = [&](int nc, int bb) {
        const int n0 = nc * 32;
        {
            size_t gb = ((size_t)b * Ndim + n0 + fb_r0) * HQdim + (fb_c0 < 128 ? fb_c0 : fb_c0 - 128);
            const bf16* sh = (fb_c0 < 128) ? (g_ekv_hi + gb) : (g_ek_hi + gb);
            const bf16* sl = (fb_c0 < 128) ? (g_ekv_lo + gb) : (g_ek_lo + gb);
            uint32_t dh = saddr(&B_hi[bb * AFT_B_ELEMS + fb_r0 * AFT_SB + fb_c0]);
            uint32_t dl = saddr(&B_lo[bb * AFT_B_ELEMS + fb_r0 * AFT_SB + fb_c0]);
            cpa16(dh, sh); cpa16(dl, sl);
        }
        {
            size_t gb = ((size_t)b * Ndim + n0 + fb_r1) * HQdim + (fb_c1 < 128 ? fb_c1 : fb_c1 - 128);
            const bf16* sh = (fb_c1 < 128) ? (g_ekv_hi + gb) : (g_ek_hi + gb);
            const bf16* sl = (fb_c1 < 128) ? (g_ekv_lo + gb) : (g_ek_lo + gb);
            uint32_t dh = saddr(&B_hi[bb * AFT_B_ELEMS + fb_r1 * AFT_SB + fb_c1]);
            uint32_t dl = saddr(&B_lo[bb * AFT_B_ELEMS + fb_r1 * AFT_SB + fb_c1]);
            cpa16(dh, sh); cpa16(dl, sl);
        }
    };
    auto loadA = [&](int nc) {
        const int n0 = nc * 32;
        size_t g0 = ((size_t)b * Pdim + p0 + fa_r0) * Ndim + n0 + fa_c0;
        size_t g1 = ((size_t)b * Pdim + p0 + fa_r1) * Ndim + n0 + fa_c1;
        pf_cd[0] = *reinterpret_cast<const float4*>(cur_dist + g0);
        pf_nm[0] = *reinterpret_cast<const float4*>(ninf + g0);
        pf_cd[1] = *reinterpret_cast<const float4*>(cur_dist + g1);
        pf_nm[1] = *reinterpret_cast<const float4*>(ninf + g1);
    };
    auto storeA = [&](int bb) {
#pragma unroll
        for (int t = 0; t < 2; t++) {
            int r = t ? fa_r1 : fa_r0, c4 = t ? fa_c1 : fa_c0;
            float4 cd = pf_cd[t], nm = pf_nm[t];
            float e0 = expf(nm.x - c2 * cd.x);
            float e1 = expf(nm.y - c2 * cd.y);
            float e2 = expf(nm.z - c2 * cd.z);
            float e3 = expf(nm.w - c2 * cd.w);
            union { bf16 bv[4]; uint2 u; } H, L;
            split_bf(e0, H.bv[0], L.bv[0]);
            split_bf(e1, H.bv[1], L.bv[1]);
            split_bf(e2, H.bv[2], L.bv[2]);
            split_bf(e3, H.bv[3], L.bv[3]);
            *reinterpret_cast<uint2*>(&A_hi[bb * AFT_A_ELEMS + r * AFT_SA + c4]) = H.u;
            *reinterpret_cast<uint2*>(&A_lo[bb * AFT_A_ELEMS + r * AFT_SA + c4]) = L.u;
        }
    };

    // ---- prologue: fill buffer 0
    loadA(0);
    issueB(0, 0);
    CPA_COMMIT;
    storeA(0);
    CPA_WAIT0;
    __syncthreads();

    for (int nc = 0; nc < 32; nc++) {
        const int bb = nc & 1;
        const bool pf = (nc + 1 < 32);
        if (pf) {
            issueB(nc + 1, bb ^ 1);
            CPA_COMMIT;
            loadA(nc + 1);
        }
        // ---- mma on buffer bb
        const bf16* Ah = A_hi + bb * AFT_A_ELEMS;
        const bf16* Al = A_lo + bb * AFT_A_ELEMS;
        const bf16* Bh = B_hi + bb * AFT_B_ELEMS;
        const bf16* Bl = B_lo + bb * AFT_B_ELEMS;
#pragma unroll
        for (int kk = 0; kk < 2; kk++) {
            uint32_t ah[2][4], al[2][4];
            const int arow = l & 15;
            const int acol = kk * 16 + ((l >> 1) & 8);
#pragma unroll
            for (int i = 0; i < 2; i++) {
                ldsm4(ah[i], saddr(&Ah[(wm * 32 + i * 16 + arow) * AFT_SA + acol]));
                ldsm4(al[i], saddr(&Al[(wm * 32 + i * 16 + arow) * AFT_SA + acol]));
            }
            const int brow = kk * 16 + (l & 15);
#pragma unroll
            for (int j = 0; j < 4; j++) {
                uint32_t bh[4], bl[4];
                const int bcol = wn * 64 + j * 16 + ((l >> 1) & 8);
                ldsm4t(bh, saddr(&Bh[brow * AFT_SB + bcol]));
                ldsm4t(bl, saddr(&Bl[brow * AFT_SB + bcol]));
#pragma unroll
                for (int i = 0; i < 2; i++) {
                    mma_bf16(C[i][2 * j],     ah[i], bh);
                    mma_bf16(C[i][2 * j],     al[i], bh);
                    mma_bf16(C[i][2 * j],     ah[i], bl);
                    mma_bf16(C[i][2 * j + 1], ah[i], bh + 2);
                    mma_bf16(C[i][2 * j + 1], al[i], bh + 2);
                    mma_bf16(C[i][2 * j + 1], ah[i], bl + 2);
                }
            }
        }
        if (pf) storeA(bb ^ 1);
        CPA_WAIT0;
        __syncthreads();
    }

    // ---- epilogue: den warps (wn>=2) stage to smem, num warps combine
    const int qr = l >> 2, qc = (l & 3) * 2;
    if (wn >= 2) {
        const int dbase = (wn - 2) * 64;
#pragma unroll
        for (int i = 0; i < 2; i++) {
            int r0 = wm * 32 + i * 16 + qr;
#pragma unroll
            for (int j = 0; j < 8; j++) {
                int d = dbase + j * 8 + qc;
                den_s[r0 * 132 + d]           = C[i][j][0];
                den_s[r0 * 132 + d + 1]       = C[i][j][1];
                den_s[(r0 + 8) * 132 + d]     = C[i][j][2];
                den_s[(r0 + 8) * 132 + d + 1] = C[i][j][3];
            }
        }
    }
    __syncthreads();
    if (wn < 2) {
        const int dbase = wn * 64;
#pragma unroll
        for (int i = 0; i < 2; i++) {
#pragma unroll
            for (int h = 0; h < 2; h++) {
                int r = wm * 32 + i * 16 + qr + h * 8;
                size_t sb = ((size_t)b * Pdim + p0 + r) * HQdim;
#pragma unroll
                for (int j = 0; j < 8; j++) {
                    int d = dbase + j * 8 + qc;
                    float nu0 = C[i][j][2 * h], nu1 = C[i][j][2 * h + 1];
                    float de0 = den_s[r * 132 + d], de1 = den_s[r * 132 + d + 1];
                    float2 sg = *reinterpret_cast<const float2*>(g_sigq + sb + d);
                    float a0 = sg.x * nan2num(nu0) / (nan2num(de0) + 1e-20f);
                    float a1 = sg.y * nan2num(nu1) / (nan2num(de1) + 1e-20f);
                    bf16 h0, l0, h1, l1;
                    split_bf(a0, h0, l0);
                    split_bf(a1, h1, l1);
                    __nv_bfloat162 hh; hh.x = h0; hh.y = h1;
                    __nv_bfloat162 ll; ll.x = l0; ll.y = l1;
                    *reinterpret_cast<__nv_bfloat162*>(&g_aft_hi[sb + d]) = hh;
                    *reinterpret_cast<__nv_bfloat162*>(&g_aft_lo[sb + d]) = ll;
                }
            }
        }
    }
}

// ============================================================================
// K4: bf16x3 score GEMM + fused softmax. 512 threads / 16 warps, warp tile
// 32x32. Full A (aft 128x128 hi/lo) resident in smem (loaded once, cp.async);
// B chunks (32x128 encT) double-buffered with cp.async.
// ============================================================================
#define SC_SA 136
#define SC_SB 136
#define SC_A_ELEMS (128 * SC_SA)
#define SC_B_ELEMS (32 * SC_SB)
#define SC_SMEM_BYTES ((2 * SC_A_ELEMS + 2 * 2 * SC_B_ELEMS) * 2)   // 104448

__global__ __launch_bounds__(512, 1) void k_score_mma(
    const float* __restrict__ cur_dist,
    const float* __restrict__ ninf,
    const float* __restrict__ ls,
    const float* __restrict__ palpha,
    float* __restrict__ out)
{
    extern __shared__ __align__(16) char sm_raw[];
    bf16* A_hi = reinterpret_cast<bf16*>(sm_raw);        // 128*136
    bf16* A_lo = A_hi + SC_A_ELEMS;
    bf16* B_hi = A_lo + SC_A_ELEMS;                      // [2][32*136]
    bf16* B_lo = B_hi + 2 * SC_B_ELEMS;
    __shared__ float partial[128 * 4];
    __shared__ float inv_s[128];

    const int b  = blockIdx.x;
    const int p0 = blockIdx.y * 128;
    const int tid = threadIdx.x;
    const int l   = tid & 31;
    const int wid = tid >> 5;
    const int wm  = wid >> 2;     // 0..3
    const int wn  = wid & 3;      // 0..3
    const float cp = ls[0] * palpha[0];
    const float inv_se = 1.0f / SQRT_E_F;
    const int qr = l >> 2, qc = (l & 3) * 2;

    // B-fill mapping: 512 uint4 slots (32 rows x 16 groups), 1 per thread
    const int gb_r = tid >> 4, gb_c = (tid & 15) * 8;

    auto issueB = [&](int chunk, int bb) {
        const int nt = chunk >> 2, kc = chunk & 3;
        size_t g = ((size_t)b * Edim + kc * 32 + gb_r) * Ndim + nt * 128 + gb_c;
        cpa16(saddr(&B_hi[bb * SC_B_ELEMS + gb_r * SC_SB + gb_c]), g_encT_hi + g);
        cpa16(saddr(&B_lo[bb * SC_B_ELEMS + gb_r * SC_SB + gb_c]), g_encT_lo + g);
    };

    // ---- prologue: async-load full A (128x128 hi/lo) + first B chunk
#pragma unroll
    for (int t = 0; t < 4; t++) {
        int i8 = tid + t * 512;                 // 2048 slots: 128 rows x 16 groups
        int r = i8 >> 4, c8 = (i8 & 15) * 8;
        size_t g = ((size_t)b * Pdim + p0 + r) * HQdim + c8;
        cpa16(saddr(&A_hi[r * SC_SA + c8]), g_aft_hi + g);
        cpa16(saddr(&A_lo[r * SC_SA + c8]), g_aft_lo + g);
    }
    issueB(0, 0);
    CPA_COMMIT;
    CPA_WAIT0;
    __syncthreads();

    float C[2][4][4];
#pragma unroll
    for (int i = 0; i < 2; i++)
#pragma unroll
        for (int j = 0; j < 4; j++)
#pragma unroll
            for (int r = 0; r < 4; r++) C[i][j][r] = 0.f;

    float rs[2][2];
#pragma unroll
    for (int i = 0; i < 2; i++) { rs[i][0] = 0.f; rs[i][1] = 0.f; }

    for (int c = 0; c < 32; c++) {
        const int bb = c & 1;
        const int nt = c >> 2, kc = c & 3;
        if (c + 1 < 32) { issueB(c + 1, bb ^ 1); CPA_COMMIT; }

        const bf16* Bh = B_hi + bb * SC_B_ELEMS;
        const bf16* Bl = B_lo + bb * SC_B_ELEMS;
#pragma unroll
        for (int kk = 0; kk < 2; kk++) {
            uint32_t ah[2][4], al[2][4];
            const int arow = l & 15;
            const int acol = kc * 32 + kk * 16 + ((l >> 1) & 8);
#pragma unroll
            for (int i = 0; i < 2; i++) {
                ldsm4(ah[i], saddr(&A_hi[(wm * 32 + i * 16 + arow) * SC_SA + acol]));
                ldsm4(al[i], saddr(&A_lo[(wm * 32 + i * 16 + arow) * SC_SA + acol]));
            }
            const int brow = kk * 16 + (l & 15);
#pragma unroll
            for (int j2 = 0; j2 < 2; j2++) {
                uint32_t bh[4], bl[4];
                const int bcol = wn * 32 + j2 * 16 + ((l >> 1) & 8);
                ldsm4t(bh, saddr(&Bh[brow * SC_SB + bcol]));
                ldsm4t(bl, saddr(&Bl[brow * SC_SB + bcol]));
#pragma unroll
                for (int i = 0; i < 2; i++) {
                    mma_bf16(C[i][2 * j2],     ah[i], bh);
                    mma_bf16(C[i][2 * j2],     al[i], bh);
                    mma_bf16(C[i][2 * j2],     ah[i], bl);
                    mma_bf16(C[i][2 * j2 + 1], ah[i], bh + 2);
                    mma_bf16(C[i][2 * j2 + 1], al[i], bh + 2);
                    mma_bf16(C[i][2 * j2 + 1], ah[i], bl + 2);
                }
            }
        }
        CPA_WAIT0;
        __syncthreads();

        if (kc == 3) {
            // epilogue for n-tile nt
#pragma unroll
            for (int i = 0; i < 2; i++) {
                int r = wm * 32 + i * 16 + qr;
#pragma unroll
                for (int j = 0; j < 4; j++) {
                    int n = nt * 128 + wn * 32 + j * 8 + qc;
                    size_t g0 = ((size_t)b * Pdim + p0 + r) * Ndim + n;
                    size_t g1 = g0 + (size_t)8 * Ndim;
                    float2 cd0 = *reinterpret_cast<const float2*>(cur_dist + g0);
                    float2 nm0 = *reinterpret_cast<const float2*>(ninf + g0);
                    float2 cd1 = *reinterpret_cast<const float2*>(cur_dist + g1);
                    float2 nm1 = *reinterpret_cast<const float2*>(ninf + g1);
                    float e00 = expf(CLIP_F * tanhf(C[i][j][0] * inv_se - cp * cd0.x) + nm0.x);
                    float e01 = expf(CLIP_F * tanhf(C[i][j][1] * inv_se - cp * cd0.y) + nm0.y);
                    float e10 = expf(CLIP_F * tanhf(C[i][j][2] * inv_se - cp * cd1.x) + nm1.x);
                    float e11 = expf(CLIP_F * tanhf(C[i][j][3] * inv_se - cp * cd1.y) + nm1.y);
                    float2 o0 = {e00, e01};
                    float2 o1 = {e10, e11};
                    *reinterpret_cast<float2*>(out + g0) = o0;
                    *reinterpret_cast<float2*>(out + g1) = o1;
                    rs[i][0] += e00 + e01;
                    rs[i][1] += e10 + e11;
#pragma unroll
                    for (int rr = 0; rr < 4; rr++) C[i][j][rr] = 0.f;
                }
            }
        }
    }
    // ---- rowsum reduce: quad shfl then across wn warps
#pragma unroll
    for (int i = 0; i < 2; i++)
#pragma unroll
        for (int h = 0; h < 2; h++) {
            float v = rs[i][h];
            v += __shfl_xor_sync(0xffffffffu, v, 1);
            v += __shfl_xor_sync(0xffffffffu, v, 2);
            rs[i][h] = v;
        }
    if ((l & 3) == 0) {
#pragma unroll
        for (int i = 0; i < 2; i++) {
            partial[(wm * 32 + i * 16 + (l >> 2)) * 4 + wn]     = rs[i][0];
            partial[(wm * 32 + i * 16 + (l >> 2) + 8) * 4 + wn] = rs[i][1];
        }
    }
    __syncthreads();
    if (tid < 128) {
        float s = partial[tid * 4] + partial[tid * 4 + 1] +
                  partial[tid * 4 + 2] + partial[tid * 4 + 3];
        inv_s[tid] = 1.0f / s;
    }
    __syncthreads();
    // ---- normalize (L2-hot re-read of this block's out region)
    const size_t obase4 = (((size_t)b * Pdim + p0) * Ndim) >> 2;
    float4* out4 = reinterpret_cast<float4*>(out);
#pragma unroll 4
    for (int t = 0; t < 64; t++) {
        int i4 = tid + t * 512;
        int r = i4 >> 8;
        float4 v = __ldcg(out4 + obase4 + i4);
        float s = inv_s[r];
        v.x *= s; v.y *= s; v.z *= s; v.w *= s;
        out4[obase4 + i4] = v;
    }
}

// ============================================================================
extern "C" void kernel_launch(void* const* d_in, const int* in_sizes, int n_in,
                              void* d_out, int out_size)
{
    const float* enc    = (const float*)d_in[0];
    const float* eq1    = (const float*)d_in[1];
    const float* eq2    = (const float*)d_in[2];
    const float* elast  = (const float*)d_in[3];
    const float* load_  = (const float*)d_in[4];
    const float* left_  = (const float*)d_in[5];
    const float* cdist  = (const float*)d_in[6];
    const float* lscale = (const float*)d_in[7];
    const float* ninf   = (const float*)d_in[8];
    const float* Wq1    = (const float*)d_in[9];
    const float* Wq2    = (const float*)d_in[10];
    const float* Wql    = (const float*)d_in[11];
    const float* Wk     = (const float*)d_in[12];
    const float* Wv     = (const float*)d_in[13];
    const float* aalpha = (const float*)d_in[14];
    const float* palpha = (const float*)d_in[15];
    float* out = (float*)d_out;

    cudaFuncSetAttribute(k_aft_mma, cudaFuncAttributeMaxDynamicSharedMemorySize,
                         AFT_SMEM_BYTES);
    cudaFuncSetAttribute(k_score_mma, cudaFuncAttributeMaxDynamicSharedMemorySize,
                         SC_SMEM_BYTES);

    k_prep_enc<<<dim3(Bdim, Ndim / 128), 256>>>(enc);
    k_proj_kv<<<dim3(Bdim, Ndim / 64), 256>>>(enc, Wk, Wv);
    k_proj_q<<<dim3(Bdim, Pdim / 64), 256>>>(eq1, eq2, elast, Wq1, Wq2, Wql, load_, left_);
    k_aft_mma<<<dim3(Bdim, Pdim / 128), 512, AFT_SMEM_BYTES>>>(cdist, ninf, lscale, aalpha);
    k_score_mma<<<dim3(Bdim, Pdim / 128), 512, SC_SMEM_BYTES>>>(cdist, ninf, lscale, palpha, out);
}